// round 4
// baseline (speedup 1.0000x reference)
#include <cuda_runtime.h>

typedef unsigned long long u64;

#define DEPTH   64
#define DD      5
#define RPT     4     // rows per thread
#define G       2     // f32x2 groups per thread (2 rows each)
#define TPB     128
#define LSTRIDE 6     // u64 per output row: w0,w1,w2,w3,w4,b (each duplicated)

// Duplicated weight table in the constant bank: warp-uniform loads go through
// the uniform-const port (LDCU), bypassing the L1tex/LSU path entirely.
__constant__ u64  c_wd[DEPTH * DD * LSTRIDE];   // 64*30*8 = 15360 B
__constant__ float c_wo[8];                     // [0..4]=W_out, [5]=b_out

// Staging scratch (device globals; no allocation).
__device__ u64  d_scratch_wd[DEPTH * DD * LSTRIDE];
__device__ float d_scratch_wo[8];

__device__ __forceinline__ u64 fma2(u64 a, u64 b, u64 c) {
    u64 d;
    asm("fma.rn.f32x2 %0, %1, %2, %3;" : "=l"(d) : "l"(a), "l"(b), "l"(c));
    return d;
}

union U2F2 { u64 u; float2 f; };

__device__ __forceinline__ u64 pack2(float lo, float hi) {
    U2F2 t; t.f.x = lo; t.f.y = hi;
    return t.u;
}

// ReLU on both packed halves: register-pair reinterpret -> exactly 2 FMNMX.
__device__ __forceinline__ u64 relu2(u64 v) {
    U2F2 t; t.u = v;
    t.f.x = fmaxf(t.f.x, 0.0f);
    t.f.y = fmaxf(t.f.y, 0.0f);
    return t.u;
}

__global__ void prep_kernel(const float* __restrict__ Ws,
                            const float* __restrict__ bs,
                            const float* __restrict__ Wo,
                            const float* __restrict__ bo)
{
    int l = threadIdx.x;
    if (l < DEPTH) {
        for (int j = 0; j < DD; j++) {
            u64* dst = &d_scratch_wd[(l * DD + j) * LSTRIDE];
            for (int i = 0; i < DD; i++) {
                unsigned u = __float_as_uint(Ws[l * 25 + j * DD + i]);
                dst[i] = (u64)u | ((u64)u << 32);
            }
            unsigned ub = __float_as_uint(bs[l * DD + j]);
            dst[DD] = (u64)ub | ((u64)ub << 32);
        }
    }
    if (l < 8) {
        float v = (l < DD) ? Wo[l] : (l == DD ? bo[0] : 0.0f);
        d_scratch_wo[l] = v;
    }
}

__global__ __launch_bounds__(TPB)
void mlp5_kernel(const float* __restrict__ x,
                 float* __restrict__ out,
                 int batch)
{
    int t = blockIdx.x * TPB + threadIdx.x;
    int row0 = t * RPT;
    if (row0 >= batch) return;

    // Load 4 rows x 5 feats = 20 floats = 5 x float4 (80B per thread).
    float xs[RPT * DD];
    const float4* xp = (const float4*)(x + (size_t)row0 * DD);
    #pragma unroll
    for (int i = 0; i < RPT * DD / 4; i++)
        ((float4*)xs)[i] = xp[i];

    // Pack rows pairwise into f32x2 registers: h[g][i] = {row(2g)[i], row(2g+1)[i]}
    u64 h[G][DD];
    #pragma unroll
    for (int g = 0; g < G; g++)
        #pragma unroll
        for (int i = 0; i < DD; i++)
            h[g][i] = pack2(xs[(2 * g) * DD + i], xs[(2 * g + 1) * DD + i]);

    #pragma unroll 1
    for (int l = 0; l < DEPTH; l++) {
        int base = l * (DD * LSTRIDE);

        u64 acc[G][DD];
        #pragma unroll
        for (int j = 0; j < DD; j++) {
            // Direct __constant__ indexing (uniform address) -> LDC/LDCU,
            // bypassing the LSU/L1tex path that bound rounds 1-3.
            u64 w0 = c_wd[base + j * LSTRIDE + 0];
            u64 w1 = c_wd[base + j * LSTRIDE + 1];
            u64 w2 = c_wd[base + j * LSTRIDE + 2];
            u64 w3 = c_wd[base + j * LSTRIDE + 3];
            u64 w4 = c_wd[base + j * LSTRIDE + 4];
            u64 bb = c_wd[base + j * LSTRIDE + 5];
            #pragma unroll
            for (int g = 0; g < G; g++) {
                u64 a = fma2(h[g][0], w0, bb);
                a = fma2(h[g][1], w1, a);
                a = fma2(h[g][2], w2, a);
                a = fma2(h[g][3], w3, a);
                a = fma2(h[g][4], w4, a);
                acc[g][j] = a;
            }
        }

        #pragma unroll
        for (int g = 0; g < G; g++)
            #pragma unroll
            for (int j = 0; j < DD; j++)
                h[g][j] = relu2(acc[g][j]);
    }

    // Final Linear(5,1) from constant bank
    float res[RPT];
    #pragma unroll
    for (int g = 0; g < G; g++) {
        float lo = c_wo[5], hi = c_wo[5];
        #pragma unroll
        for (int i = 0; i < DD; i++) {
            U2F2 t; t.u = h[g][i];
            lo = fmaf(t.f.x, c_wo[i], lo);
            hi = fmaf(t.f.y, c_wo[i], hi);
        }
        res[2 * g]     = lo;
        res[2 * g + 1] = hi;
    }
    ((float4*)(out + row0))[0] = make_float4(res[0], res[1], res[2], res[3]);
}

extern "C" void kernel_launch(void* const* d_in, const int* in_sizes, int n_in,
                              void* d_out, int out_size)
{
    const float* x  = (const float*)d_in[0];
    const float* Ws = (const float*)d_in[1];
    const float* bs = (const float*)d_in[2];
    const float* Wo = (const float*)d_in[3];
    const float* bo = (const float*)d_in[4];
    float* out = (float*)d_out;

    int batch = in_sizes[0] / DD;            // 1048576

    // Stage duplicated weights into the constant bank (all async, capturable).
    prep_kernel<<<1, 128>>>(Ws, bs, Wo, bo);

    void* p_wd = nullptr;
    void* p_wo = nullptr;
    cudaGetSymbolAddress(&p_wd, d_scratch_wd);
    cudaGetSymbolAddress(&p_wo, d_scratch_wo);
    cudaMemcpyToSymbolAsync(c_wd, p_wd, sizeof(u64) * DEPTH * DD * LSTRIDE, 0,
                            cudaMemcpyDeviceToDevice, 0);
    cudaMemcpyToSymbolAsync(c_wo, p_wo, sizeof(float) * 8, 0,
                            cudaMemcpyDeviceToDevice, 0);

    int threads = (batch + RPT - 1) / RPT;   // 262144
    int blocks = (threads + TPB - 1) / TPB;  // 2048
    mlp5_kernel<<<blocks, TPB>>>(x, out, batch);
}

// round 7
// speedup vs baseline: 1.6834x; 1.6834x over previous
#include <cuda_runtime.h>

typedef unsigned long long u64;

#define DEPTH   64
#define DD      5
#define RPT     6     // rows per thread
#define G       3     // f32x2 groups per thread (2 rows each)
#define TPB     128
#define LSTRIDE 6     // u64 per output row: w0,w1,w2,w3,w4,b (each duplicated)

__device__ __forceinline__ u64 fma2(u64 a, u64 b, u64 c) {
    u64 d;
    asm("fma.rn.f32x2 %0, %1, %2, %3;" : "=l"(d) : "l"(a), "l"(b), "l"(c));
    return d;
}

union U2F2 { u64 u; float2 f; };

__device__ __forceinline__ u64 pack2(float lo, float hi) {
    U2F2 t; t.f.x = lo; t.f.y = hi;
    return t.u;
}

// ReLU on both packed halves: register-pair reinterpret -> exactly 2 FMNMX.
__device__ __forceinline__ u64 relu2(u64 v) {
    U2F2 t; t.u = v;
    t.f.x = fmaxf(t.f.x, 0.0f);
    t.f.y = fmaxf(t.f.y, 0.0f);
    return t.u;
}

__global__ __launch_bounds__(TPB)
void mlp5_kernel(const float* __restrict__ x,
                 const float* __restrict__ Ws,
                 const float* __restrict__ bs,
                 const float* __restrict__ Wo,
                 const float* __restrict__ bo,
                 float* __restrict__ out,
                 int batch)
{
    // Compact duplicated-weight table: 30 u64 per layer (15.4 KB total),
    // every scalar stored as a (v,v) u64 pair -> single LDS is a ready f32x2
    // multiplier. Row stride 6 u64 = 48 B keeps ulonglong2 loads 16B-aligned.
    __shared__ u64 wd[DEPTH * DD * LSTRIDE];

    for (int idx = threadIdx.x; idx < DEPTH * DD * LSTRIDE; idx += TPB) {
        int l = idx / (DD * LSTRIDE), k = idx % (DD * LSTRIDE);
        int j = k / LSTRIDE, i = k % LSTRIDE;
        float v = (i < DD) ? Ws[l * 25 + j * DD + i] : bs[l * DD + j];
        unsigned u = __float_as_uint(v);
        wd[idx] = (u64)u | ((u64)u << 32);
    }
    __syncthreads();

    int t = blockIdx.x * TPB + threadIdx.x;
    int row0 = t * RPT;
    if (row0 >= batch) return;

    // Load 6 rows x 5 feats = 30 floats = 15 x float2 (120 B per thread,
    // 8B-aligned for every thread). Tail thread takes the guarded scalar path.
    float xs[RPT * DD];
    if (row0 + RPT <= batch) {
        const float2* xp = (const float2*)(x + (size_t)row0 * DD);
        #pragma unroll
        for (int i = 0; i < RPT * DD / 2; i++)
            ((float2*)xs)[i] = xp[i];
    } else {
        int nvalid = (batch - row0) * DD;
        #pragma unroll
        for (int i = 0; i < RPT * DD; i++)
            xs[i] = (i < nvalid) ? x[(size_t)row0 * DD + i] : 0.0f;
    }

    // Pack rows pairwise into f32x2 registers: h[g][i] = {row(2g)[i], row(2g+1)[i]}
    u64 h[G][DD];
    #pragma unroll
    for (int g = 0; g < G; g++)
        #pragma unroll
        for (int i = 0; i < DD; i++)
            h[g][i] = pack2(xs[(2 * g) * DD + i], xs[(2 * g + 1) * DD + i]);

    #pragma unroll 1
    for (int l = 0; l < DEPTH; l++) {
        const u64* wl = &wd[l * (DD * LSTRIDE)];

        u64 acc[G][DD];
        #pragma unroll
        for (int j = 0; j < DD; j++) {
            // 3 x LDS.128 per output row: {w0,w1}, {w2,w3}, {w4,b}
            ulonglong2 w01 = *(const ulonglong2*)(wl + j * LSTRIDE + 0);
            ulonglong2 w23 = *(const ulonglong2*)(wl + j * LSTRIDE + 2);
            ulonglong2 w4b = *(const ulonglong2*)(wl + j * LSTRIDE + 4);
            #pragma unroll
            for (int g = 0; g < G; g++) {
                u64 a = fma2(h[g][0], w01.x, w4b.y);
                a = fma2(h[g][1], w01.y, a);
                a = fma2(h[g][2], w23.x, a);
                a = fma2(h[g][3], w23.y, a);
                a = fma2(h[g][4], w4b.x, a);
                acc[g][j] = a;
            }
        }

        #pragma unroll
        for (int g = 0; g < G; g++)
            #pragma unroll
            for (int j = 0; j < DD; j++)
                h[g][j] = relu2(acc[g][j]);
    }

    // Final Linear(5,1)
    float wo[DD];
    #pragma unroll
    for (int i = 0; i < DD; i++) wo[i] = Wo[i];
    float bb = bo[0];

    float res[RPT];
    #pragma unroll
    for (int g = 0; g < G; g++) {
        float lo = bb, hi = bb;
        #pragma unroll
        for (int i = 0; i < DD; i++) {
            U2F2 t2; t2.u = h[g][i];
            lo = fmaf(t2.f.x, wo[i], lo);
            hi = fmaf(t2.f.y, wo[i], hi);
        }
        res[2 * g]     = lo;
        res[2 * g + 1] = hi;
    }
    // 3 x float2 stores (row0 multiple of 6 -> 8B aligned), pair-guarded for tail.
    #pragma unroll
    for (int k = 0; k < RPT / 2; k++)
        if (row0 + 2 * k + 2 <= batch)
            *(float2*)(out + row0 + 2 * k) = make_float2(res[2 * k], res[2 * k + 1]);
}

extern "C" void kernel_launch(void* const* d_in, const int* in_sizes, int n_in,
                              void* d_out, int out_size)
{
    const float* x  = (const float*)d_in[0];
    const float* Ws = (const float*)d_in[1];
    const float* bs = (const float*)d_in[2];
    const float* Wo = (const float*)d_in[3];
    const float* bo = (const float*)d_in[4];
    float* out = (float*)d_out;

    int batch = in_sizes[0] / DD;                      // 1048576
    int rows_per_cta = TPB * RPT;                      // 768
    int blocks = (batch + rows_per_cta - 1) / rows_per_cta;  // 1366
    mlp5_kernel<<<blocks, TPB>>>(x, Ws, bs, Wo, bo, out, batch);
}